// round 13
// baseline (speedup 1.0000x reference)
#include <cuda_runtime.h>

#define BB 32
#define NN 784
#define CC 256
#define FF 1024
#define MM (BB*NN)      // 25088
#define HEADS 8
#define DIMH 32

typedef unsigned long long u64;

// ---- f32x2 packed-math helpers ----
__device__ __forceinline__ u64 pk2(float lo, float hi) {
    u64 r; asm("mov.b64 %0,{%1,%2};" : "=l"(r) : "f"(lo), "f"(hi)); return r;
}
__device__ __forceinline__ void upk2(u64 v, float& lo, float& hi) {
    asm("mov.b64 {%0,%1},%2;" : "=f"(lo), "=f"(hi) : "l"(v));
}
__device__ __forceinline__ void fma2(u64& d, u64 a, u64 b) {
    asm("fma.rn.f32x2 %0,%1,%2,%3;" : "=l"(d) : "l"(a), "l"(b), "l"(d));
}

// ---------------- scratch ----------------
__device__ float g_x[(size_t)MM * FF];
__device__ float g_attn[(size_t)MM * 512];
__device__ float g_sum[FF];
__device__ float g_sumsq[FF];
__device__ float g_affa[FF];
__device__ float g_affb[FF];

__global__ void zero_stats_kernel() {
    int i = blockIdx.x * blockDim.x + threadIdx.x;
    if (i < FF) { g_sum[i] = 0.f; g_sumsq[i] = 0.f; }
}

// ---------------- SGEMM: 128x128 block, 8x8 micro (split +-64) — r11 validated ----------------
template<int KTOT, int LDA, int LDB, int LDC, bool STATS>
__global__ __launch_bounds__(256, 2) void sgemm_kernel(
    const float* __restrict__ A, const float* __restrict__ Bm, float* __restrict__ C)
{
    __shared__ __align__(16) float As[16][128];
    __shared__ __align__(16) float Bs[16][128];
    __shared__ float csum[128], csq[128];

    const int m0 = blockIdx.y * 128;
    const int n0 = blockIdx.x * 128;
    const int tid = threadIdx.x;
    const int tx = tid & 15, ty = tid >> 4;
    const int tx4 = tx * 4, ty4 = ty * 4;

    float acc[8][8] = {};

    for (int k0 = 0; k0 < KTOT; k0 += 16) {
        #pragma unroll
        for (int r = 0; r < 2; r++) {
            int f4 = tid + r * 256;
            int m = f4 >> 2, kq = f4 & 3;
            float4 v = *reinterpret_cast<const float4*>(&A[(size_t)(m0 + m) * LDA + k0 + kq * 4]);
            As[kq*4+0][m] = v.x; As[kq*4+1][m] = v.y; As[kq*4+2][m] = v.z; As[kq*4+3][m] = v.w;
        }
        #pragma unroll
        for (int r = 0; r < 2; r++) {
            int f4 = tid + r * 256;
            int k = f4 >> 5, n4 = f4 & 31;
            float4 v = *reinterpret_cast<const float4*>(&Bm[(size_t)(k0 + k) * LDB + n0 + n4 * 4]);
            *reinterpret_cast<float4*>(&Bs[k][n4 * 4]) = v;
        }
        __syncthreads();
        #pragma unroll
        for (int k = 0; k < 16; k++) {
            float4 a0 = *reinterpret_cast<const float4*>(&As[k][ty4]);
            float4 a1 = *reinterpret_cast<const float4*>(&As[k][64 + ty4]);
            float4 b0 = *reinterpret_cast<const float4*>(&Bs[k][tx4]);
            float4 b1 = *reinterpret_cast<const float4*>(&Bs[k][64 + tx4]);
            float av[8] = {a0.x, a0.y, a0.z, a0.w, a1.x, a1.y, a1.z, a1.w};
            float bv[8] = {b0.x, b0.y, b0.z, b0.w, b1.x, b1.y, b1.z, b1.w};
            #pragma unroll
            for (int i = 0; i < 8; i++)
                #pragma unroll
                for (int j = 0; j < 8; j++)
                    acc[i][j] = fmaf(av[i], bv[j], acc[i][j]);
        }
        __syncthreads();
    }

    #pragma unroll
    for (int i = 0; i < 8; i++) {
        int row = m0 + ((i < 4) ? (ty4 + i) : (64 + ty4 + i - 4));
        *reinterpret_cast<float4*>(&C[(size_t)row * LDC + n0 + tx4]) =
            make_float4(acc[i][0], acc[i][1], acc[i][2], acc[i][3]);
        *reinterpret_cast<float4*>(&C[(size_t)row * LDC + n0 + 64 + tx4]) =
            make_float4(acc[i][4], acc[i][5], acc[i][6], acc[i][7]);
    }

    if (STATS) {
        if (tid < 128) { csum[tid] = 0.f; csq[tid] = 0.f; }
        __syncthreads();
        #pragma unroll
        for (int j = 0; j < 8; j++) {
            int col = (j < 4) ? (tx4 + j) : (64 + tx4 + j - 4);
            float s = 0.f, sq = 0.f;
            #pragma unroll
            for (int i = 0; i < 8; i++) { float v = acc[i][j]; s += v; sq = fmaf(v, v, sq); }
            atomicAdd(&csum[col], s);
            atomicAdd(&csq[col], sq);
        }
        __syncthreads();
        if (tid < 128) {
            atomicAdd(&g_sum[n0 + tid], csum[tid]);
            atomicAdd(&g_sumsq[n0 + tid], csq[tid]);
        }
    }
}

// ---------------- BN finalize ----------------
__global__ void bn_finalize_kernel(const float* __restrict__ bn_scale) {
    int f = blockIdx.x * blockDim.x + threadIdx.x;
    if (f < FF) {
        float mean = g_sum[f] * (1.f / MM);
        float var  = g_sumsq[f] * (1.f / MM) - mean * mean;
        float r = rsqrtf(var + 1e-5f);
        float a = r * bn_scale[f];
        g_affa[f] = a;
        g_affb[f] = -mean * a;
    }
}

// ---------------- fused flash attention: QT=112, KT=64, 224 threads, 16q/warp ----------------
// r12 structure (validated traffic win: L1 52%) with register diet for 3 CTAs/SM:
// S-phase split over k-halves (jh outer, s[4][4] per half) -> peak live ~96 regs.
// tx = tid&7 (k / vd), ty = tid>>3 (0..27, 4 q each). Warp = 4 ty x 8 tx = 16 q rows.
//   Qs [112][32] group-swizzled by (q>>2)&7 | Ks [64][32] swizzled | Vs [64][64] plain
//   Ss [112][64] col-group swizzled by (q>>2)&7
// Fixed-shift softmax p = exp(s + bias - 20); l via tx == (kk&7); 8-lane shfl reduce.
#define EXP_SHIFT 20.0f
#define AT_SMEM_FLOATS (112*32 + 64*32 + 64*64 + 112*64 + 256)
__global__ __launch_bounds__(224, 3) void attention_kernel(
    const float* __restrict__ bias, float* __restrict__ out)
{
    extern __shared__ __align__(16) float sm[];
    float* Qs = sm;                 // 3584
    float* Ks = sm + 3584;          // 2048
    float* Vs = sm + 5632;          // 4096
    float* Ss = sm + 9728;          // 7168 (112*64)
    float* cA = sm + 16896;         // 128
    float* cB = sm + 17024;         // 128

    const int tid = threadIdx.x;
    const int tx = tid & 7, ty = tid >> 3;     // ty 0..27
    const int tx4 = tx * 4, ty4 = ty * 4;
    const int tyg = ty & 7;                    // (q>>2)&7 for q = ty4+i (i<4)
    const int q0 = blockIdx.x * 112;
    const int h  = blockIdx.y;
    const int b  = blockIdx.z;

    if (tid < 128) {
        int seg = tid >> 5, d = tid & 31;
        int f = seg * 256 + h * 32 + d;
        cA[tid] = g_affa[f];
        cB[tid] = g_affb[f];
    }
    __syncthreads();

    // Q tile [112,32], normalized, group-swizzled by (q>>2)&7 (784 = 7*112 -> no q mask)
    for (int idx = tid; idx < 112 * 32; idx += 224) {
        int q = idx >> 5, d = idx & 31;
        float v = fmaf(g_x[(size_t)(b * NN + q0 + q) * FF + h * 32 + d], cA[d], cB[d]);
        Qs[q * 32 + ((((d >> 2) ^ ((q >> 2) & 7)) << 2) | (d & 3))] = v;
    }

    u64 acc2[4][4] = {};   // [i][vd pairs: {tx4,+1},{+2,+3},{32+tx4,+1},{+2,+3}]
    float lacc[4] = {0.f, 0.f, 0.f, 0.f};

    for (int kc = 0; kc < 13; kc++) {
        const int k0 = kc * 64;
        __syncthreads();   // protect Ks/Vs/Ss from previous-iteration consumers

        // K chunk [64,32], XOR-swizzled float4 groups (r7 pattern)
        for (int idx = tid; idx < 64 * 32; idx += 224) {
            int k = idx >> 5, d = idx & 31;
            int row = k0 + k;
            float v = (row < NN) ? fmaf(g_x[(size_t)(b * NN + row) * FF + 256 + h * 32 + d],
                                        cA[32 + d], cB[32 + d]) : 0.f;
            Ks[k * 32 + ((((d >> 2) ^ ((k >> 2) & 7)) << 2) | (d & 3))] = v;
        }
        // V chunk [64,64] (v1 | v2), plain
        for (int idx = tid; idx < 64 * 64; idx += 224) {
            int k = idx >> 6, d = idx & 63;
            int row = k0 + k;
            int col = 512 + ((d >> 5) << 8) + h * 32 + (d & 31);
            float v = (row < NN) ? fmaf(g_x[(size_t)(b * NN + row) * FF + col],
                                        cA[64 + d], cB[64 + d]) : 0.f;
            Vs[k * 64 + d] = v;
        }
        __syncthreads();

        // ---- S = Q K^T: two k-halves sequentially (s[4][4] each -> low peak regs) ----
        #pragma unroll
        for (int jh = 0; jh < 2; jh++) {
            float s[4][4] = {};
            #pragma unroll
            for (int dq = 0; dq < 8; dq++) {
                float4 qa[4];
                #pragma unroll
                for (int i = 0; i < 4; i++)
                    qa[i] = *reinterpret_cast<const float4*>(
                        &Qs[(ty4 + i) * 32 + ((dq ^ tyg) << 2)]);
                float4 kb[4];
                #pragma unroll
                for (int j = 0; j < 4; j++)
                    kb[j] = *reinterpret_cast<const float4*>(
                        &Ks[(jh * 32 + tx4 + j) * 32 + ((dq ^ tx) << 2)]);
                #pragma unroll
                for (int i = 0; i < 4; i++)
                    #pragma unroll
                    for (int j = 0; j < 4; j++) {
                        float a = s[i][j];
                        a = fmaf(qa[i].x, kb[j].x, a);
                        a = fmaf(qa[i].y, kb[j].y, a);
                        a = fmaf(qa[i].z, kb[j].z, a);
                        a = fmaf(qa[i].w, kb[j].w, a);
                        s[i][j] = a;
                    }
            }
            // exp + bias, store this half to Ss (col-group swizzled by tyg)
            const bool kvalid = (k0 + jh * 32 + tx4 + 3) < NN;   // 784 % 4 == 0
            const int c4 = (jh << 3) | ((tx ^ tyg) & 7);          // swizzled group
            #pragma unroll
            for (int i = 0; i < 4; i++) {
                int q = ty4 + i;
                float4 o;
                if (kvalid) {
                    float4 bi = *reinterpret_cast<const float4*>(
                        &bias[(size_t)(q0 + q) * NN + k0 + jh * 32 + tx4]);
                    o.x = __expf(s[i][0] + bi.x - EXP_SHIFT);
                    o.y = __expf(s[i][1] + bi.y - EXP_SHIFT);
                    o.z = __expf(s[i][2] + bi.z - EXP_SHIFT);
                    o.w = __expf(s[i][3] + bi.w - EXP_SHIFT);
                } else {
                    o = make_float4(0.f, 0.f, 0.f, 0.f);
                }
                *reinterpret_cast<float4*>(&Ss[q * 64 + (c4 << 2)]) = o;
            }
        }
        __syncthreads();

        // ---- PV accumulate: 4q x 8vd f32x2 + free l accumulation ----
        #pragma unroll
        for (int kk = 0; kk < 16; kk++) {
            const int rc4 = (kk & 8) | ((kk ^ tyg) & 7);   // swizzled read group
            float4 P[4];
            #pragma unroll
            for (int i = 0; i < 4; i++)
                P[i] = *reinterpret_cast<const float4*>(&Ss[(ty4 + i) * 64 + (rc4 << 2)]);
            if (tx == (kk & 7)) {   // each kk-slice counted exactly once across tx
                #pragma unroll
                for (int i = 0; i < 4; i++)
                    lacc[i] += (P[i].x + P[i].y) + (P[i].z + P[i].w);
            }
            #pragma unroll
            for (int c = 0; c < 4; c++) {
                int k = kk * 4 + c;
                ulonglong2 v0 = *reinterpret_cast<const ulonglong2*>(&Vs[k * 64 + tx4]);
                ulonglong2 v1 = *reinterpret_cast<const ulonglong2*>(&Vs[k * 64 + 32 + tx4]);
                #pragma unroll
                for (int i = 0; i < 4; i++) {
                    float p = (c == 0) ? P[i].x : (c == 1) ? P[i].y : (c == 2) ? P[i].z : P[i].w;
                    u64 pp = pk2(p, p);
                    fma2(acc2[i][0], pp, v0.x);
                    fma2(acc2[i][1], pp, v0.y);
                    fma2(acc2[i][2], pp, v1.x);
                    fma2(acc2[i][3], pp, v1.y);
                }
            }
        }
    }

    // ---- reduce l across the 8-lane tx group ----
    #pragma unroll
    for (int i = 0; i < 4; i++) {
        #pragma unroll
        for (int d = 1; d < 8; d <<= 1)
            lacc[i] += __shfl_xor_sync(0xffffffffu, lacc[i], d);
    }

    // ---- epilogue: /l, hard_swish, write [ (b*N+q), h*64 + {tx4, 32+tx4} ] ----
    #pragma unroll
    for (int i = 0; i < 4; i++) {
        int q = ty4 + i;
        float inv = 1.0f / lacc[i];
        float v[8];
        upk2(acc2[i][0], v[0], v[1]);
        upk2(acc2[i][1], v[2], v[3]);
        upk2(acc2[i][2], v[4], v[5]);
        upk2(acc2[i][3], v[6], v[7]);
        #pragma unroll
        for (int j = 0; j < 8; j++) {
            v[j] *= inv;
            v[j] = v[j] * __saturatef((v[j] + 3.0f) * (1.0f / 6.0f));
        }
        float* op = &out[((size_t)(b * NN + q0 + q)) * 512 + h * 64];
        *reinterpret_cast<float4*>(op + tx4)      = make_float4(v[0], v[1], v[2], v[3]);
        *reinterpret_cast<float4*>(op + 32 + tx4) = make_float4(v[4], v[5], v[6], v[7]);
    }
}

// ---------------- launch ----------------
extern "C" void kernel_launch(void* const* d_in, const int* in_sizes, int n_in,
                              void* d_out, int out_size) {
    const float* inputs    = (const float*)d_in[0];
    const float* w_qkv     = (const float*)d_in[1];
    const float* bn_scale  = (const float*)d_in[2];
    const float* attn_bias = (const float*)d_in[3];
    const float* w_out     = (const float*)d_in[4];
    float* out = (float*)d_out;

    float *px, *pattn;
    cudaGetSymbolAddress((void**)&px, g_x);
    cudaGetSymbolAddress((void**)&pattn, g_attn);

    const int at_smem = AT_SMEM_FLOATS * 4;   // 68608 bytes
    cudaFuncSetAttribute(attention_kernel,
                         cudaFuncAttributeMaxDynamicSharedMemorySize, at_smem);

    zero_stats_kernel<<<4, 256>>>();
    sgemm_kernel<256, 256, 1024, 1024, true><<<dim3(8, 196), 256>>>(inputs, w_qkv, px);
    bn_finalize_kernel<<<4, 256>>>(bn_scale);
    attention_kernel<<<dim3(7, HEADS, BB), 224, at_smem>>>(attn_bias, pattn);
    sgemm_kernel<512, 512, 256, 256, false><<<dim3(2, 196), 256>>>(pattn, w_out, out);
}

// round 14
// speedup vs baseline: 2.0323x; 2.0323x over previous
#include <cuda_runtime.h>

#define BB 32
#define NN 784
#define CC 256
#define FF 1024
#define MM (BB*NN)      // 25088
#define HEADS 8
#define DIMH 32

typedef unsigned long long u64;

// ---- f32x2 packed-math helpers ----
__device__ __forceinline__ u64 pk2(float lo, float hi) {
    u64 r; asm("mov.b64 %0,{%1,%2};" : "=l"(r) : "f"(lo), "f"(hi)); return r;
}
__device__ __forceinline__ void upk2(u64 v, float& lo, float& hi) {
    asm("mov.b64 {%0,%1},%2;" : "=f"(lo), "=f"(hi) : "l"(v));
}
__device__ __forceinline__ void fma2(u64& d, u64 a, u64 b) {
    asm("fma.rn.f32x2 %0,%1,%2,%3;" : "=l"(d) : "l"(a), "l"(b), "l"(d));
}

// ---------------- scratch ----------------
__device__ float g_x[(size_t)MM * FF];
__device__ float g_attn[(size_t)MM * 512];
__device__ float g_sum[FF];
__device__ float g_sumsq[FF];
__device__ float g_affa[FF];
__device__ float g_affb[FF];

__global__ void zero_stats_kernel() {
    int i = blockIdx.x * blockDim.x + threadIdx.x;
    if (i < FF) { g_sum[i] = 0.f; g_sumsq[i] = 0.f; }
}

// ---------------- SGEMM: 128x128 block, 8x8 micro (split +-64) — r11 validated ----------------
template<int KTOT, int LDA, int LDB, int LDC, bool STATS>
__global__ __launch_bounds__(256, 2) void sgemm_kernel(
    const float* __restrict__ A, const float* __restrict__ Bm, float* __restrict__ C)
{
    __shared__ __align__(16) float As[16][128];
    __shared__ __align__(16) float Bs[16][128];
    __shared__ float csum[128], csq[128];

    const int m0 = blockIdx.y * 128;
    const int n0 = blockIdx.x * 128;
    const int tid = threadIdx.x;
    const int tx = tid & 15, ty = tid >> 4;
    const int tx4 = tx * 4, ty4 = ty * 4;

    float acc[8][8] = {};

    for (int k0 = 0; k0 < KTOT; k0 += 16) {
        #pragma unroll
        for (int r = 0; r < 2; r++) {
            int f4 = tid + r * 256;
            int m = f4 >> 2, kq = f4 & 3;
            float4 v = *reinterpret_cast<const float4*>(&A[(size_t)(m0 + m) * LDA + k0 + kq * 4]);
            As[kq*4+0][m] = v.x; As[kq*4+1][m] = v.y; As[kq*4+2][m] = v.z; As[kq*4+3][m] = v.w;
        }
        #pragma unroll
        for (int r = 0; r < 2; r++) {
            int f4 = tid + r * 256;
            int k = f4 >> 5, n4 = f4 & 31;
            float4 v = *reinterpret_cast<const float4*>(&Bm[(size_t)(k0 + k) * LDB + n0 + n4 * 4]);
            *reinterpret_cast<float4*>(&Bs[k][n4 * 4]) = v;
        }
        __syncthreads();
        #pragma unroll
        for (int k = 0; k < 16; k++) {
            float4 a0 = *reinterpret_cast<const float4*>(&As[k][ty4]);
            float4 a1 = *reinterpret_cast<const float4*>(&As[k][64 + ty4]);
            float4 b0 = *reinterpret_cast<const float4*>(&Bs[k][tx4]);
            float4 b1 = *reinterpret_cast<const float4*>(&Bs[k][64 + tx4]);
            float av[8] = {a0.x, a0.y, a0.z, a0.w, a1.x, a1.y, a1.z, a1.w};
            float bv[8] = {b0.x, b0.y, b0.z, b0.w, b1.x, b1.y, b1.z, b1.w};
            #pragma unroll
            for (int i = 0; i < 8; i++)
                #pragma unroll
                for (int j = 0; j < 8; j++)
                    acc[i][j] = fmaf(av[i], bv[j], acc[i][j]);
        }
        __syncthreads();
    }

    #pragma unroll
    for (int i = 0; i < 8; i++) {
        int row = m0 + ((i < 4) ? (ty4 + i) : (64 + ty4 + i - 4));
        *reinterpret_cast<float4*>(&C[(size_t)row * LDC + n0 + tx4]) =
            make_float4(acc[i][0], acc[i][1], acc[i][2], acc[i][3]);
        *reinterpret_cast<float4*>(&C[(size_t)row * LDC + n0 + 64 + tx4]) =
            make_float4(acc[i][4], acc[i][5], acc[i][6], acc[i][7]);
    }

    if (STATS) {
        if (tid < 128) { csum[tid] = 0.f; csq[tid] = 0.f; }
        __syncthreads();
        #pragma unroll
        for (int j = 0; j < 8; j++) {
            int col = (j < 4) ? (tx4 + j) : (64 + tx4 + j - 4);
            float s = 0.f, sq = 0.f;
            #pragma unroll
            for (int i = 0; i < 8; i++) { float v = acc[i][j]; s += v; sq = fmaf(v, v, sq); }
            atomicAdd(&csum[col], s);
            atomicAdd(&csq[col], sq);
        }
        __syncthreads();
        if (tid < 128) {
            atomicAdd(&g_sum[n0 + tid], csum[tid]);
            atomicAdd(&g_sumsq[n0 + tid], csq[tid]);
        }
    }
}

// ---------------- BN finalize ----------------
__global__ void bn_finalize_kernel(const float* __restrict__ bn_scale) {
    int f = blockIdx.x * blockDim.x + threadIdx.x;
    if (f < FF) {
        float mean = g_sum[f] * (1.f / MM);
        float var  = g_sumsq[f] * (1.f / MM) - mean * mean;
        float r = rsqrtf(var + 1e-5f);
        float a = r * bn_scale[f];
        g_affa[f] = a;
        g_affb[f] = -mean * a;
    }
}

// ---------------- normalize x in place: x = x*affa + affb (one pass, float4) ----------------
__global__ __launch_bounds__(256) void normalize_kernel() {
    size_t i = (size_t)blockIdx.x * 256 + threadIdx.x;      // float4 index; grid covers MM*FF/4
    int c4 = (int)(i & 255);                                // FF/4 = 256 float4 cols per row
    float4 v = reinterpret_cast<float4*>(g_x)[i];
    float4 a = reinterpret_cast<float4*>(g_affa)[c4];
    float4 bb = reinterpret_cast<float4*>(g_affb)[c4];
    v.x = fmaf(v.x, a.x, bb.x);
    v.y = fmaf(v.y, a.y, bb.y);
    v.z = fmaf(v.z, a.z, bb.z);
    v.w = fmaf(v.w, a.w, bb.w);
    reinterpret_cast<float4*>(g_x)[i] = v;
}

// ---------------- fused flash attention: QT=56, KT=64, 224 thr, 4x4 — r11 core ----------------
// x pre-normalized -> fills are raw float4 copies (no cA/cB, no affine in fills).
// Fixed-shift softmax p = exp(s + bias - 20); l via tx==kk trick; layouts validated r5/r7/r11.
#define EXP_SHIFT 20.0f
__global__ __launch_bounds__(224, 4) void attention_kernel(
    const float* __restrict__ bias, float* __restrict__ out)
{
    __shared__ __align__(16) float Qs[56 * 32];
    __shared__ __align__(16) float Ks[64 * 32];
    __shared__ __align__(16) float Vs[64 * 64];
    __shared__ __align__(16) float Ss[56 * 68];

    const int tid = threadIdx.x;
    const int tx = tid & 15, ty = tid >> 4;       // ty 0..13
    const int tx4 = tx * 4, ty4 = ty * 4;
    const int q0 = blockIdx.x * 56;
    const int h  = blockIdx.y;
    const int b  = blockIdx.z;

    // Q tile [56,32]: 448 float4, 2 per thread
    #pragma unroll
    for (int r = 0; r < 2; r++) {
        int f = tid + r * 224;
        int q = f >> 3, d4 = f & 7;
        float4 v = *reinterpret_cast<const float4*>(
            &g_x[(size_t)(b * NN + q0 + q) * FF + h * 32 + d4 * 4]);
        *reinterpret_cast<float4*>(&Qs[q * 32 + d4 * 4]) = v;
    }

    u64 acc2[4][2] = {};            // out[q 4][vd pairs 2], packed along vd
    float lacc[4] = {0.f, 0.f, 0.f, 0.f};

    for (int kc = 0; kc < 13; kc++) {
        const int k0 = kc * 64;
        __syncthreads();  // protect Ks/Vs/Ss from previous-iteration consumers

        // K chunk [64,32]: 512 float4, XOR-swizzled groups
        for (int f = tid; f < 512; f += 224) {
            int k = f >> 3, d4 = f & 7;
            int row = k0 + k;
            float4 v = make_float4(0.f, 0.f, 0.f, 0.f);
            if (row < NN)
                v = *reinterpret_cast<const float4*>(
                    &g_x[(size_t)(b * NN + row) * FF + 256 + h * 32 + d4 * 4]);
            *reinterpret_cast<float4*>(&Ks[k * 32 + ((d4 ^ ((k >> 2) & 7)) << 2)]) = v;
        }
        // V chunk [64,64]: 1024 float4, plain
        for (int f = tid; f < 1024; f += 224) {
            int k = f >> 4, t = f & 15;
            int part = t >> 3, d4 = t & 7;
            int row = k0 + k;
            float4 v = make_float4(0.f, 0.f, 0.f, 0.f);
            if (row < NN)
                v = *reinterpret_cast<const float4*>(
                    &g_x[(size_t)(b * NN + row) * FF + 512 + part * 256 + h * 32 + d4 * 4]);
            *reinterpret_cast<float4*>(&Vs[k * 64 + part * 32 + d4 * 4]) = v;
        }
        __syncthreads();

        // ---- S = Q K^T (f32x2 packed along d), then P = exp(S + bias - 20) ----
        {
            u64 s2[4][4] = {};
            #pragma unroll
            for (int dq = 0; dq < 8; dq++) {
                ulonglong2 kb[4];
                #pragma unroll
                for (int j = 0; j < 4; j++)
                    kb[j] = *reinterpret_cast<const ulonglong2*>(
                        &Ks[(tx4 + j) * 32 + ((dq ^ (tx & 7)) << 2)]);
                #pragma unroll
                for (int i = 0; i < 4; i++) {
                    ulonglong2 qa = *reinterpret_cast<const ulonglong2*>(
                        &Qs[(ty4 + i) * 32 + dq * 4]);
                    #pragma unroll
                    for (int j = 0; j < 4; j++) {
                        fma2(s2[i][j], qa.x, kb[j].x);
                        fma2(s2[i][j], qa.y, kb[j].y);
                    }
                }
            }
            if (k0 + tx4 + 3 < NN) {   // 784 % 4 == 0 -> whole float4 valid or invalid
                #pragma unroll
                for (int i = 0; i < 4; i++) {
                    float4 bi = *reinterpret_cast<const float4*>(
                        &bias[(size_t)(q0 + ty4 + i) * NN + k0 + tx4]);
                    float lo, hi;
                    float p0, p1, p2, p3;
                    upk2(s2[i][0], lo, hi); p0 = __expf(lo + hi + bi.x - EXP_SHIFT);
                    upk2(s2[i][1], lo, hi); p1 = __expf(lo + hi + bi.y - EXP_SHIFT);
                    upk2(s2[i][2], lo, hi); p2 = __expf(lo + hi + bi.z - EXP_SHIFT);
                    upk2(s2[i][3], lo, hi); p3 = __expf(lo + hi + bi.w - EXP_SHIFT);
                    *reinterpret_cast<float4*>(&Ss[(ty4 + i) * 68 + tx4]) =
                        make_float4(p0, p1, p2, p3);
                }
            } else {
                #pragma unroll
                for (int i = 0; i < 4; i++)
                    *reinterpret_cast<float4*>(&Ss[(ty4 + i) * 68 + tx4]) =
                        make_float4(0.f, 0.f, 0.f, 0.f);
            }
        }
        __syncthreads();

        // ---- PV accumulate (f32x2 packed along vd) + free l accumulation ----
        #pragma unroll
        for (int kk = 0; kk < 16; kk++) {
            float4 P[4];
            #pragma unroll
            for (int i = 0; i < 4; i++)
                P[i] = *reinterpret_cast<const float4*>(&Ss[(ty4 + i) * 68 + kk * 4]);
            if (tx == kk) {   // each kk-slice counted exactly once across the tx group
                #pragma unroll
                for (int i = 0; i < 4; i++)
                    lacc[i] += (P[i].x + P[i].y) + (P[i].z + P[i].w);
            }
            #pragma unroll
            for (int c = 0; c < 4; c++) {
                ulonglong2 vv = *reinterpret_cast<const ulonglong2*>(
                    &Vs[(kk * 4 + c) * 64 + tx4]);
                #pragma unroll
                for (int i = 0; i < 4; i++) {
                    float p = (c == 0) ? P[i].x : (c == 1) ? P[i].y : (c == 2) ? P[i].z : P[i].w;
                    u64 pp = pk2(p, p);
                    fma2(acc2[i][0], pp, vv.x);
                    fma2(acc2[i][1], pp, vv.y);
                }
            }
        }
    }

    // ---- reduce l across the 16-lane tx group ----
    #pragma unroll
    for (int i = 0; i < 4; i++) {
        #pragma unroll
        for (int d = 1; d < 16; d <<= 1)
            lacc[i] += __shfl_xor_sync(0xffffffffu, lacc[i], d);
    }

    // ---- epilogue: /l, hard_swish, write [ (b*N+q), h*64 + vd ] ----
    #pragma unroll
    for (int i = 0; i < 4; i++) {
        int q = ty4 + i;
        float inv = 1.0f / lacc[i];
        float v0, v1, v2, v3;
        upk2(acc2[i][0], v0, v1);
        upk2(acc2[i][1], v2, v3);
        v0 *= inv; v1 *= inv; v2 *= inv; v3 *= inv;
        float o[4];
        o[0] = v0 * __saturatef((v0 + 3.0f) * (1.0f / 6.0f));
        o[1] = v1 * __saturatef((v1 + 3.0f) * (1.0f / 6.0f));
        o[2] = v2 * __saturatef((v2 + 3.0f) * (1.0f / 6.0f));
        o[3] = v3 * __saturatef((v3 + 3.0f) * (1.0f / 6.0f));
        *reinterpret_cast<float4*>(&out[((size_t)(b * NN + q0 + q)) * 512 + h * 64 + tx4]) =
            make_float4(o[0], o[1], o[2], o[3]);
    }
}

// ---------------- launch ----------------
extern "C" void kernel_launch(void* const* d_in, const int* in_sizes, int n_in,
                              void* d_out, int out_size) {
    const float* inputs    = (const float*)d_in[0];
    const float* w_qkv     = (const float*)d_in[1];
    const float* bn_scale  = (const float*)d_in[2];
    const float* attn_bias = (const float*)d_in[3];
    const float* w_out     = (const float*)d_in[4];
    float* out = (float*)d_out;

    float *px, *pattn;
    cudaGetSymbolAddress((void**)&px, g_x);
    cudaGetSymbolAddress((void**)&pattn, g_attn);

    zero_stats_kernel<<<4, 256>>>();
    sgemm_kernel<256, 256, 1024, 1024, true><<<dim3(8, 196), 256>>>(inputs, w_qkv, px);
    bn_finalize_kernel<<<4, 256>>>(bn_scale);
    normalize_kernel<<<MM, 256>>>();   // MM*FF/4 float4s = MM blocks * 256 threads
    attention_kernel<<<dim3(14, HEADS, BB), 224>>>(attn_bias, pattn);
    sgemm_kernel<512, 512, 256, 256, false><<<dim3(2, 196), 256>>>(pattn, w_out, out);
}

// round 16
// speedup vs baseline: 2.2850x; 1.1243x over previous
#include <cuda_runtime.h>
#include <cuda_bf16.h>

#define BB 32
#define NN 784
#define CC 256
#define FF 1024
#define MM (BB*NN)      // 25088
#define HEADS 8
#define DIMH 32

typedef unsigned long long u64;

// ---- f32x2 packed-math helpers (attention) ----
__device__ __forceinline__ u64 pk2(float lo, float hi) {
    u64 r; asm("mov.b64 %0,{%1,%2};" : "=l"(r) : "f"(lo), "f"(hi)); return r;
}
__device__ __forceinline__ void upk2(u64 v, float& lo, float& hi) {
    asm("mov.b64 {%0,%1},%2;" : "=f"(lo), "=f"(hi) : "l"(v));
}
__device__ __forceinline__ void fma2(u64& d, u64 a, u64 b) {
    asm("fma.rn.f32x2 %0,%1,%2,%3;" : "=l"(d) : "l"(a), "l"(b), "l"(d));
}

__device__ __forceinline__ unsigned smem_u32(const void* p) {
    unsigned a;
    asm("{ .reg .u64 t; cvta.to.shared.u64 t, %1; cvt.u32.u64 %0, t; }" : "=r"(a) : "l"(p));
    return a;
}

// ---------------- scratch ----------------
__device__ float g_x[(size_t)MM * FF];
__device__ float g_attn[(size_t)MM * 512];
__device__ float g_sum[FF];
__device__ float g_sumsq[FF];
__device__ float g_affa[FF];
__device__ float g_affb[FF];
__device__ __nv_bfloat16 g_wq_h[(size_t)CC * FF];    // [k=256][n=1024], native layout
__device__ __nv_bfloat16 g_wq_l[(size_t)CC * FF];
__device__ __nv_bfloat16 g_wo_h[(size_t)512 * CC];   // [k=512][n=256]
__device__ __nv_bfloat16 g_wo_l[(size_t)512 * CC];

__global__ void zero_stats_kernel() {
    int i = blockIdx.x * blockDim.x + threadIdx.x;
    if (i < FF) { g_sum[i] = 0.f; g_sumsq[i] = 0.f; }
}

// ---------------- split weights into bf16 hi/lo (no transpose) ----------------
__global__ __launch_bounds__(256) void conv_w_kernel(
    const float* __restrict__ wq, const float* __restrict__ wo)
{
    int i = blockIdx.x * 256 + threadIdx.x;
    if (i < CC * FF) {
        float v = wq[i];
        __nv_bfloat16 h = __float2bfloat16(v);
        g_wq_h[i] = h;
        g_wq_l[i] = __float2bfloat16(v - __bfloat162float(h));
    }
    if (i < 512 * CC) {
        float v = wo[i];
        __nv_bfloat16 h = __float2bfloat16(v);
        g_wo_h[i] = h;
        g_wo_l[i] = __float2bfloat16(v - __bfloat162float(h));
    }
}

// ---------------- mma.sync bf16 split GEMM: C[M,N] = A[M,K](fp32) * B[K,N] ----------------
// 128x128 CTA tile, 8 warps (2m x 4n), warp tile 64x32 (4x4 m16n8k16 frags).
// A fp32 -> bf16 hi/lo split in the fill; B pre-split bf16 [k][n] consumed via ldmatrix.trans.
// Smem swizzles (16B chunks): A chunk = seg ^ ((m>>1)&3); B chunk = n16 ^ (k&7).
template<int KTOT, int LDB, int LDC>
__global__ __launch_bounds__(256) void mma_gemm_kernel(
    const float* __restrict__ A,
    const __nv_bfloat16* __restrict__ Bh_g, const __nv_bfloat16* __restrict__ Bl_g,
    float* __restrict__ C)
{
    __shared__ __align__(16) uint4 Ah[128 * 4], Al[128 * 4];   // [m][chunk] 8 bf16/chunk
    __shared__ __align__(16) uint4 Bh[32 * 16], Bl[32 * 16];   // [k][chunk]

    const int tid = threadIdx.x;
    const int lane = tid & 31, wid = tid >> 5;
    const int wm = (wid & 1) * 64, wn = (wid >> 1) * 32;
    const int m0 = blockIdx.x * 128, n0 = blockIdx.y * 128;

    float acc[4][4][4] = {};   // [fm][fn][reg]

    for (int k0 = 0; k0 < KTOT; k0 += 32) {
        __syncthreads();   // prior chunk's frags consumed
        // ---- A fill: 128 m x 32 k, fp32 -> hi/lo bf16, 8 k per op ----
        #pragma unroll
        for (int it = 0; it < 2; it++) {
            int f = tid + it * 256;
            int m = f >> 2, seg = f & 3;
            const float4* gp = reinterpret_cast<const float4*>(
                &A[(size_t)(m0 + m) * KTOT + k0 + seg * 8]);
            float4 va = gp[0], vb = gp[1];
            float v[8] = {va.x, va.y, va.z, va.w, vb.x, vb.y, vb.z, vb.w};
            unsigned hh[4], ll[4];
            #pragma unroll
            for (int j = 0; j < 4; j++) {
                __nv_bfloat16 h0 = __float2bfloat16(v[2*j]);
                __nv_bfloat16 h1 = __float2bfloat16(v[2*j+1]);
                __nv_bfloat16 l0 = __float2bfloat16(v[2*j]   - __bfloat162float(h0));
                __nv_bfloat16 l1 = __float2bfloat16(v[2*j+1] - __bfloat162float(h1));
                hh[j] = (unsigned)__bfloat16_as_ushort(h0) | ((unsigned)__bfloat16_as_ushort(h1) << 16);
                ll[j] = (unsigned)__bfloat16_as_ushort(l0) | ((unsigned)__bfloat16_as_ushort(l1) << 16);
            }
            int ch = seg ^ ((m >> 1) & 3);
            Ah[m * 4 + ch] = make_uint4(hh[0], hh[1], hh[2], hh[3]);
            Al[m * 4 + ch] = make_uint4(ll[0], ll[1], ll[2], ll[3]);
        }
        // ---- B fill: 32 k x 128 n, pre-split bf16 copies ----
        #pragma unroll
        for (int it = 0; it < 2; it++) {
            int f = tid + it * 256;
            int k = f >> 4, ch = f & 15;
            size_t gi = (size_t)(k0 + k) * LDB + n0 + ch * 8;
            uint4 vh = *reinterpret_cast<const uint4*>(&Bh_g[gi]);
            uint4 vl = *reinterpret_cast<const uint4*>(&Bl_g[gi]);
            int cs = ch ^ (k & 7);
            Bh[k * 16 + cs] = vh;
            Bl[k * 16 + cs] = vl;
        }
        __syncthreads();

        // ---- two k16 steps ----
        #pragma unroll
        for (int ks = 0; ks < 2; ks++) {
            unsigned ah[4][4], al[4][4], bh[2][4], bl[2][4];
            #pragma unroll
            for (int fm = 0; fm < 4; fm++) {
                int row = wm + fm * 16 + (lane & 15);
                int ch = (ks * 2 + (lane >> 4)) ^ ((row >> 1) & 3);
                unsigned adh = smem_u32(&Ah[row * 4 + ch]);
                unsigned adl = smem_u32(&Al[row * 4 + ch]);
                asm volatile("ldmatrix.sync.aligned.m8n8.x4.shared.b16 {%0,%1,%2,%3}, [%4];"
                    : "=r"(ah[fm][0]), "=r"(ah[fm][1]), "=r"(ah[fm][2]), "=r"(ah[fm][3]) : "r"(adh));
                asm volatile("ldmatrix.sync.aligned.m8n8.x4.shared.b16 {%0,%1,%2,%3}, [%4];"
                    : "=r"(al[fm][0]), "=r"(al[fm][1]), "=r"(al[fm][2]), "=r"(al[fm][3]) : "r"(adl));
            }
            #pragma unroll
            for (int np = 0; np < 2; np++) {
                int k = ks * 16 + (lane & 15);
                int nc = (wn >> 3) + np * 2 + (lane >> 4);
                int cs = nc ^ (k & 7);
                unsigned adh = smem_u32(&Bh[k * 16 + cs]);
                unsigned adl = smem_u32(&Bl[k * 16 + cs]);
                asm volatile("ldmatrix.sync.aligned.m8n8.x4.trans.shared.b16 {%0,%1,%2,%3}, [%4];"
                    : "=r"(bh[np][0]), "=r"(bh[np][1]), "=r"(bh[np][2]), "=r"(bh[np][3]) : "r"(adh));
                asm volatile("ldmatrix.sync.aligned.m8n8.x4.trans.shared.b16 {%0,%1,%2,%3}, [%4];"
                    : "=r"(bl[np][0]), "=r"(bl[np][1]), "=r"(bl[np][2]), "=r"(bl[np][3]) : "r"(adl));
            }
            #pragma unroll
            for (int fm = 0; fm < 4; fm++)
                #pragma unroll
                for (int fn = 0; fn < 4; fn++) {
                    unsigned b0h = bh[fn >> 1][(fn & 1) * 2], b1h = bh[fn >> 1][(fn & 1) * 2 + 1];
                    unsigned b0l = bl[fn >> 1][(fn & 1) * 2], b1l = bl[fn >> 1][(fn & 1) * 2 + 1];
                    float* d = acc[fm][fn];
                    asm volatile("mma.sync.aligned.m16n8k16.row.col.f32.bf16.bf16.f32 "
                        "{%0,%1,%2,%3}, {%4,%5,%6,%7}, {%8,%9}, {%0,%1,%2,%3};"
                        : "+f"(d[0]), "+f"(d[1]), "+f"(d[2]), "+f"(d[3])
                        : "r"(ah[fm][0]), "r"(ah[fm][1]), "r"(ah[fm][2]), "r"(ah[fm][3]),
                          "r"(b0h), "r"(b1h));
                    asm volatile("mma.sync.aligned.m16n8k16.row.col.f32.bf16.bf16.f32 "
                        "{%0,%1,%2,%3}, {%4,%5,%6,%7}, {%8,%9}, {%0,%1,%2,%3};"
                        : "+f"(d[0]), "+f"(d[1]), "+f"(d[2]), "+f"(d[3])
                        : "r"(ah[fm][0]), "r"(ah[fm][1]), "r"(ah[fm][2]), "r"(ah[fm][3]),
                          "r"(b0l), "r"(b1l));
                    asm volatile("mma.sync.aligned.m16n8k16.row.col.f32.bf16.bf16.f32 "
                        "{%0,%1,%2,%3}, {%4,%5,%6,%7}, {%8,%9}, {%0,%1,%2,%3};"
                        : "+f"(d[0]), "+f"(d[1]), "+f"(d[2]), "+f"(d[3])
                        : "r"(al[fm][0]), "r"(al[fm][1]), "r"(al[fm][2]), "r"(al[fm][3]),
                          "r"(b0h), "r"(b1h));
                }
        }
    }

    // ---- epilogue: D frag rows l>>2 / +8, cols 2(l&3), 2(l&3)+1 ----
    #pragma unroll
    for (int fm = 0; fm < 4; fm++) {
        int r0 = m0 + wm + fm * 16 + (lane >> 2);
        #pragma unroll
        for (int fn = 0; fn < 4; fn++) {
            int c0 = n0 + wn + fn * 8 + (lane & 3) * 2;
            *reinterpret_cast<float2*>(&C[(size_t)r0 * LDC + c0]) =
                make_float2(acc[fm][fn][0], acc[fm][fn][1]);
            *reinterpret_cast<float2*>(&C[(size_t)(r0 + 8) * LDC + c0]) =
                make_float2(acc[fm][fn][2], acc[fm][fn][3]);
        }
    }
}

// ---------------- BN stats over g_x (per-feature sum/sumsq) ----------------
__global__ __launch_bounds__(128) void stats_kernel() {
    int f = blockIdx.y * 128 + threadIdx.x;
    size_t mbase = (size_t)blockIdx.x * NN;
    float s = 0.f, sq = 0.f;
    #pragma unroll 4
    for (int r = 0; r < NN; r++) {
        float v = g_x[(mbase + r) * FF + f];
        s += v; sq = fmaf(v, v, sq);
    }
    atomicAdd(&g_sum[f], s);
    atomicAdd(&g_sumsq[f], sq);
}

// ---------------- BN finalize ----------------
__global__ void bn_finalize_kernel(const float* __restrict__ bn_scale) {
    int f = blockIdx.x * blockDim.x + threadIdx.x;
    if (f < FF) {
        float mean = g_sum[f] * (1.f / MM);
        float var  = g_sumsq[f] * (1.f / MM) - mean * mean;
        float r = rsqrtf(var + 1e-5f);
        float a = r * bn_scale[f];
        g_affa[f] = a;
        g_affb[f] = -mean * a;
    }
}

// ---------------- normalize x in place ----------------
__global__ __launch_bounds__(256) void normalize_kernel() {
    size_t i = (size_t)blockIdx.x * 256 + threadIdx.x;
    int c4 = (int)(i & 255);
    float4 v = reinterpret_cast<float4*>(g_x)[i];
    float4 a = reinterpret_cast<float4*>(g_affa)[c4];
    float4 bb = reinterpret_cast<float4*>(g_affb)[c4];
    v.x = fmaf(v.x, a.x, bb.x);
    v.y = fmaf(v.y, a.y, bb.y);
    v.z = fmaf(v.z, a.z, bb.z);
    v.w = fmaf(v.w, a.w, bb.w);
    reinterpret_cast<float4*>(g_x)[i] = v;
}

// ---------------- fused flash attention (r14 verbatim): QT=56, KT=64, 224 thr, 4x4 ----------------
#define EXP_SHIFT 20.0f
__global__ __launch_bounds__(224, 4) void attention_kernel(
    const float* __restrict__ bias, float* __restrict__ out)
{
    __shared__ __align__(16) float Qs[56 * 32];
    __shared__ __align__(16) float Ks[64 * 32];
    __shared__ __align__(16) float Vs[64 * 64];
    __shared__ __align__(16) float Ss[56 * 68];

    const int tid = threadIdx.x;
    const int tx = tid & 15, ty = tid >> 4;
    const int tx4 = tx * 4, ty4 = ty * 4;
    const int q0 = blockIdx.x * 56;
    const int h  = blockIdx.y;
    const int b  = blockIdx.z;

    #pragma unroll
    for (int r = 0; r < 2; r++) {
        int f = tid + r * 224;
        int q = f >> 3, d4 = f & 7;
        float4 v = *reinterpret_cast<const float4*>(
            &g_x[(size_t)(b * NN + q0 + q) * FF + h * 32 + d4 * 4]);
        *reinterpret_cast<float4*>(&Qs[q * 32 + d4 * 4]) = v;
    }

    u64 acc2[4][2] = {};
    float lacc[4] = {0.f, 0.f, 0.f, 0.f};

    for (int kc = 0; kc < 13; kc++) {
        const int k0 = kc * 64;
        __syncthreads();

        for (int f = tid; f < 512; f += 224) {
            int k = f >> 3, d4 = f & 7;
            int row = k0 + k;
            float4 v = make_float4(0.f, 0.f, 0.f, 0.f);
            if (row < NN)
                v = *reinterpret_cast<const float4*>(
                    &g_x[(size_t)(b * NN + row) * FF + 256 + h * 32 + d4 * 4]);
            *reinterpret_cast<float4*>(&Ks[k * 32 + ((d4 ^ ((k >> 2) & 7)) << 2)]) = v;
        }
        for (int f = tid; f < 1024; f += 224) {
            int k = f >> 4, t = f & 15;
            int part = t >> 3, d4 = t & 7;
            int row = k0 + k;
            float4 v = make_float4(0.f, 0.f, 0.f, 0.f);
            if (row < NN)
                v = *reinterpret_cast<const float4*>(
                    &g_x[(size_t)(b * NN + row) * FF + 512 + part * 256 + h * 32 + d4 * 4]);
            *reinterpret_cast<float4*>(&Vs[k * 64 + part * 32 + d4 * 4]) = v;
        }
        __syncthreads();

        {
            u64 s2[4][4] = {};
            #pragma unroll
            for (int dq = 0; dq < 8; dq++) {
                ulonglong2 kb[4];
                #pragma unroll
                for (int j = 0; j < 4; j++)
                    kb[j] = *reinterpret_cast<const ulonglong2*>(
                        &Ks[(tx4 + j) * 32 + ((dq ^ (tx & 7)) << 2)]);
                #pragma unroll
                for (int i = 0; i < 4; i++) {
                    ulonglong2 qa = *reinterpret_cast<const ulonglong2*>(
                        &Qs[(ty4 + i) * 32 + dq * 4]);
                    #pragma unroll
                    for (int j = 0; j < 4; j++) {
                        fma2(s2[i][j], qa.x, kb[j].x);
                        fma2(s2[i][j], qa.y, kb[j].y);
                    }
                }
            }
            if (k0 + tx4 + 3 < NN) {
                #pragma unroll
                for (int i = 0; i < 4; i++) {
                    float4 bi = *reinterpret_cast<const float4*>(
                        &bias[(size_t)(q0 + ty4 + i) * NN + k0 + tx4]);
                    float lo, hi, p0, p1, p2, p3;
                    upk2(s2[i][0], lo, hi); p0 = __expf(lo + hi + bi.x - EXP_SHIFT);
                    upk2(s2[i][1], lo, hi); p1 = __expf(lo + hi + bi.y - EXP_SHIFT);
                    upk2(s2[i][2], lo, hi); p2 = __expf(lo + hi + bi.z - EXP_SHIFT);
                    upk2(s2[i][3], lo, hi); p3 = __expf(lo + hi + bi.w - EXP_SHIFT);
                    *reinterpret_cast<float4*>(&Ss[(ty4 + i) * 68 + tx4]) =
                        make_float4(p0, p1, p2, p3);
                }
            } else {
                #pragma unroll
                for (int i = 0; i < 4; i++)
                    *reinterpret_cast<float4*>(&Ss[(ty4 + i) * 68 + tx4]) =
                        make_float4(0.f, 0.f, 0.f, 0.f);
            }
        }
        __syncthreads();

        #pragma unroll
        for (int kk = 0; kk < 16; kk++) {
            float4 P[4];
            #pragma unroll
            for (int i = 0; i < 4; i++)
                P[i] = *reinterpret_cast<const float4*>(&Ss[(ty4 + i) * 68 + kk * 4]);
            if (tx == kk) {
                #pragma unroll
                for (int i = 0; i < 4; i++)
                    lacc[i] += (P[i].x + P[i].y) + (P[i].z + P[i].w);
            }
            #pragma unroll
            for (int c = 0; c < 4; c++) {
                ulonglong2 vv = *reinterpret_cast<const ulonglong2*>(
                    &Vs[(kk * 4 + c) * 64 + tx4]);
                #pragma unroll
                for (int i = 0; i < 4; i++) {
                    float p = (c == 0) ? P[i].x : (c == 1) ? P[i].y : (c == 2) ? P[i].z : P[i].w;
                    u64 pp = pk2(p, p);
                    fma2(acc2[i][0], pp, vv.x);
                    fma2(acc2[i][1], pp, vv.y);
                }
            }
        }
    }

    #pragma unroll
    for (int i = 0; i < 4; i++) {
        #pragma unroll
        for (int d = 1; d < 16; d <<= 1)
            lacc[i] += __shfl_xor_sync(0xffffffffu, lacc[i], d);
    }

    #pragma unroll
    for (int i = 0; i < 4; i++) {
        int q = ty4 + i;
        float inv = 1.0f / lacc[i];
        float v0, v1, v2, v3;
        upk2(acc2[i][0], v0, v1);
        upk2(acc2[i][1], v2, v3);
        v0 *= inv; v1 *= inv; v2 *= inv; v3 *= inv;
        float o[4];
        o[0] = v0 * __saturatef((v0 + 3.0f) * (1.0f / 6.0f));
        o[1] = v1 * __saturatef((v1 + 3.0f) * (1.0f / 6.0f));
        o[2] = v2 * __saturatef((v2 + 3.0f) * (1.0f / 6.0f));
        o[3] = v3 * __saturatef((v3 + 3.0f) * (1.0f / 6.0f));
        *reinterpret_cast<float4*>(&out[((size_t)(b * NN + q0 + q)) * 512 + h * 64 + tx4]) =
            make_float4(o[0], o[1], o[2], o[3]);
    }
}

// ---------------- launch ----------------
extern "C" void kernel_launch(void* const* d_in, const int* in_sizes, int n_in,
                              void* d_out, int out_size) {
    const float* inputs    = (const float*)d_in[0];
    const float* w_qkv     = (const float*)d_in[1];
    const float* bn_scale  = (const float*)d_in[2];
    const float* attn_bias = (const float*)d_in[3];
    const float* w_out     = (const float*)d_in[4];
    float* out = (float*)d_out;

    float *px, *pattn;
    cudaGetSymbolAddress((void**)&px, g_x);
    cudaGetSymbolAddress((void**)&pattn, g_attn);
    __nv_bfloat16 *pwqh, *pwql, *pwoh, *pwol;
    cudaGetSymbolAddress((void**)&pwqh, g_wq_h);
    cudaGetSymbolAddress((void**)&pwql, g_wq_l);
    cudaGetSymbolAddress((void**)&pwoh, g_wo_h);
    cudaGetSymbolAddress((void**)&pwol, g_wo_l);

    zero_stats_kernel<<<4, 256>>>();
    conv_w_kernel<<<1024, 256>>>(w_qkv, w_out);
    // x = inputs @ w_qkv  (tensor-core bf16 split)
    mma_gemm_kernel<256, 1024, 1024><<<dim3(196, 8), 256>>>(inputs, pwqh, pwql, px);
    stats_kernel<<<dim3(32, 8), 128>>>();
    bn_finalize_kernel<<<4, 256>>>(bn_scale);
    normalize_kernel<<<MM, 256>>>();
    attention_kernel<<<dim3(14, HEADS, BB), 224>>>(attn_bias, pattn);
    // out = attn @ w_out  (tensor-core bf16 split)
    mma_gemm_kernel<512, 256, 256><<<dim3(196, 2), 256>>>(pattn, pwoh, pwol, out);
}

// round 17
// speedup vs baseline: 2.3261x; 1.0180x over previous
#include <cuda_runtime.h>
#include <cuda_bf16.h>

#define BB 32
#define NN 784
#define CC 256
#define FF 1024
#define MM (BB*NN)      // 25088
#define HEADS 8
#define DIMH 32

typedef unsigned long long u64;

// ---- f32x2 packed-math helpers (attention) ----
__device__ __forceinline__ u64 pk2(float lo, float hi) {
    u64 r; asm("mov.b64 %0,{%1,%2};" : "=l"(r) : "f"(lo), "f"(hi)); return r;
}
__device__ __forceinline__ void upk2(u64 v, float& lo, float& hi) {
    asm("mov.b64 {%0,%1},%2;" : "=f"(lo), "=f"(hi) : "l"(v));
}
__device__ __forceinline__ void fma2(u64& d, u64 a, u64 b) {
    asm("fma.rn.f32x2 %0,%1,%2,%3;" : "=l"(d) : "l"(a), "l"(b), "l"(d));
}

__device__ __forceinline__ unsigned smem_u32(const void* p) {
    unsigned a;
    asm("{ .reg .u64 t; cvta.to.shared.u64 t, %1; cvt.u32.u64 %0, t; }" : "=r"(a) : "l"(p));
    return a;
}

// ---------------- scratch ----------------
__device__ float g_x[(size_t)MM * FF];
__device__ float g_attn[(size_t)MM * 512];
__device__ float g_sum[FF];
__device__ float g_sumsq[FF];
__device__ float g_affa[FF];
__device__ float g_affb[FF];
__device__ __nv_bfloat16 g_wq_h[(size_t)CC * FF];    // [k=256][n=1024], native layout
__device__ __nv_bfloat16 g_wq_l[(size_t)CC * FF];
__device__ __nv_bfloat16 g_wo_h[(size_t)512 * CC];   // [k=512][n=256]
__device__ __nv_bfloat16 g_wo_l[(size_t)512 * CC];

__global__ void zero_stats_kernel() {
    int i = blockIdx.x * blockDim.x + threadIdx.x;
    if (i < FF) { g_sum[i] = 0.f; g_sumsq[i] = 0.f; }
}

// ---------------- split weights into bf16 hi/lo (no transpose) ----------------
__global__ __launch_bounds__(256) void conv_w_kernel(
    const float* __restrict__ wq, const float* __restrict__ wo)
{
    int i = blockIdx.x * 256 + threadIdx.x;
    if (i < CC * FF) {
        float v = wq[i];
        __nv_bfloat16 h = __float2bfloat16(v);
        g_wq_h[i] = h;
        g_wq_l[i] = __float2bfloat16(v - __bfloat162float(h));
    }
    if (i < 512 * CC) {
        float v = wo[i];
        __nv_bfloat16 h = __float2bfloat16(v);
        g_wo_h[i] = h;
        g_wo_l[i] = __float2bfloat16(v - __bfloat162float(h));
    }
}

// ---------------- mma.sync bf16 split GEMM: C[M,N] = A[M,K](fp32) * B[K,N] ----------------
// 128x128 CTA tile, 8 warps (2m x 4n), warp tile 64x32 (4x4 m16n8k16 frags).
// A fp32 -> bf16 hi/lo split in the fill; B pre-split bf16 [k][n] via ldmatrix.trans.
// STATS: per-feature sum/sumsq fused into the epilogue (values already in regs).
template<int KTOT, int LDB, int LDC, bool STATS>
__global__ __launch_bounds__(256) void mma_gemm_kernel(
    const float* __restrict__ A,
    const __nv_bfloat16* __restrict__ Bh_g, const __nv_bfloat16* __restrict__ Bl_g,
    float* __restrict__ C)
{
    __shared__ __align__(16) uint4 Ah[128 * 4], Al[128 * 4];   // [m][chunk] 8 bf16/chunk
    __shared__ __align__(16) uint4 Bh[32 * 16], Bl[32 * 16];   // [k][chunk]
    __shared__ float csum[128], csq[128];

    const int tid = threadIdx.x;
    const int lane = tid & 31, wid = tid >> 5;
    const int wm = (wid & 1) * 64, wn = (wid >> 1) * 32;
    const int m0 = blockIdx.x * 128, n0 = blockIdx.y * 128;

    if (STATS) {
        if (tid < 128) { csum[tid] = 0.f; csq[tid] = 0.f; }
    }

    float acc[4][4][4] = {};   // [fm][fn][reg]

    for (int k0 = 0; k0 < KTOT; k0 += 32) {
        __syncthreads();   // prior chunk's frags consumed (also covers csum init)
        // ---- A fill: 128 m x 32 k, fp32 -> hi/lo bf16, 8 k per op ----
        #pragma unroll
        for (int it = 0; it < 2; it++) {
            int f = tid + it * 256;
            int m = f >> 2, seg = f & 3;
            const float4* gp = reinterpret_cast<const float4*>(
                &A[(size_t)(m0 + m) * KTOT + k0 + seg * 8]);
            float4 va = gp[0], vb = gp[1];
            float v[8] = {va.x, va.y, va.z, va.w, vb.x, vb.y, vb.z, vb.w};
            unsigned hh[4], ll[4];
            #pragma unroll
            for (int j = 0; j < 4; j++) {
                __nv_bfloat16 h0 = __float2bfloat16(v[2*j]);
                __nv_bfloat16 h1 = __float2bfloat16(v[2*j+1]);
                __nv_bfloat16 l0 = __float2bfloat16(v[2*j]   - __bfloat162float(h0));
                __nv_bfloat16 l1 = __float2bfloat16(v[2*j+1] - __bfloat162float(h1));
                hh[j] = (unsigned)__bfloat16_as_ushort(h0) | ((unsigned)__bfloat16_as_ushort(h1) << 16);
                ll[j] = (unsigned)__bfloat16_as_ushort(l0) | ((unsigned)__bfloat16_as_ushort(l1) << 16);
            }
            int ch = seg ^ ((m >> 1) & 3);
            Ah[m * 4 + ch] = make_uint4(hh[0], hh[1], hh[2], hh[3]);
            Al[m * 4 + ch] = make_uint4(ll[0], ll[1], ll[2], ll[3]);
        }
        // ---- B fill: 32 k x 128 n, pre-split bf16 copies ----
        #pragma unroll
        for (int it = 0; it < 2; it++) {
            int f = tid + it * 256;
            int k = f >> 4, ch = f & 15;
            size_t gi = (size_t)(k0 + k) * LDB + n0 + ch * 8;
            uint4 vh = *reinterpret_cast<const uint4*>(&Bh_g[gi]);
            uint4 vl = *reinterpret_cast<const uint4*>(&Bl_g[gi]);
            int cs = ch ^ (k & 7);
            Bh[k * 16 + cs] = vh;
            Bl[k * 16 + cs] = vl;
        }
        __syncthreads();

        // ---- two k16 steps ----
        #pragma unroll
        for (int ks = 0; ks < 2; ks++) {
            unsigned ah[4][4], al[4][4], bh[2][4], bl[2][4];
            #pragma unroll
            for (int fm = 0; fm < 4; fm++) {
                int row = wm + fm * 16 + (lane & 15);
                int ch = (ks * 2 + (lane >> 4)) ^ ((row >> 1) & 3);
                unsigned adh = smem_u32(&Ah[row * 4 + ch]);
                unsigned adl = smem_u32(&Al[row * 4 + ch]);
                asm volatile("ldmatrix.sync.aligned.m8n8.x4.shared.b16 {%0,%1,%2,%3}, [%4];"
                    : "=r"(ah[fm][0]), "=r"(ah[fm][1]), "=r"(ah[fm][2]), "=r"(ah[fm][3]) : "r"(adh));
                asm volatile("ldmatrix.sync.aligned.m8n8.x4.shared.b16 {%0,%1,%2,%3}, [%4];"
                    : "=r"(al[fm][0]), "=r"(al[fm][1]), "=r"(al[fm][2]), "=r"(al[fm][3]) : "r"(adl));
            }
            #pragma unroll
            for (int np = 0; np < 2; np++) {
                int k = ks * 16 + (lane & 15);
                int nc = (wn >> 3) + np * 2 + (lane >> 4);
                int cs = nc ^ (k & 7);
                unsigned adh = smem_u32(&Bh[k * 16 + cs]);
                unsigned adl = smem_u32(&Bl[k * 16 + cs]);
                asm volatile("ldmatrix.sync.aligned.m8n8.x4.trans.shared.b16 {%0,%1,%2,%3}, [%4];"
                    : "=r"(bh[np][0]), "=r"(bh[np][1]), "=r"(bh[np][2]), "=r"(bh[np][3]) : "r"(adh));
                asm volatile("ldmatrix.sync.aligned.m8n8.x4.trans.shared.b16 {%0,%1,%2,%3}, [%4];"
                    : "=r"(bl[np][0]), "=r"(bl[np][1]), "=r"(bl[np][2]), "=r"(bl[np][3]) : "r"(adl));
            }
            #pragma unroll
            for (int fm = 0; fm < 4; fm++)
                #pragma unroll
                for (int fn = 0; fn < 4; fn++) {
                    unsigned b0h = bh[fn >> 1][(fn & 1) * 2], b1h = bh[fn >> 1][(fn & 1) * 2 + 1];
                    unsigned b0l = bl[fn >> 1][(fn & 1) * 2], b1l = bl[fn >> 1][(fn & 1) * 2 + 1];
                    float* d = acc[fm][fn];
                    asm volatile("mma.sync.aligned.m16n8k16.row.col.f32.bf16.bf16.f32 "
                        "{%0,%1,%2,%3}, {%4,%5,%6,%7}, {%8,%9}, {%0,%1,%2,%3};"
                        : "+f"(d[0]), "+f"(d[1]), "+f"(d[2]), "+f"(d[3])
                        : "r"(ah[fm][0]), "r"(ah[fm][1]), "r"(ah[fm][2]), "r"(ah[fm][3]),
                          "r"(b0h), "r"(b1h));
                    asm volatile("mma.sync.aligned.m16n8k16.row.col.f32.bf16.bf16.f32 "
                        "{%0,%1,%2,%3}, {%4,%5,%6,%7}, {%8,%9}, {%0,%1,%2,%3};"
                        : "+f"(d[0]), "+f"(d[1]), "+f"(d[2]), "+f"(d[3])
                        : "r"(ah[fm][0]), "r"(ah[fm][1]), "r"(ah[fm][2]), "r"(ah[fm][3]),
                          "r"(b0l), "r"(b1l));
                    asm volatile("mma.sync.aligned.m16n8k16.row.col.f32.bf16.bf16.f32 "
                        "{%0,%1,%2,%3}, {%4,%5,%6,%7}, {%8,%9}, {%0,%1,%2,%3};"
                        : "+f"(d[0]), "+f"(d[1]), "+f"(d[2]), "+f"(d[3])
                        : "r"(al[fm][0]), "r"(al[fm][1]), "r"(al[fm][2]), "r"(al[fm][3]),
                          "r"(b0h), "r"(b1h));
                }
        }
    }

    // ---- epilogue: D frag rows l>>2 / +8, cols 2(l&3), 2(l&3)+1 ----
    #pragma unroll
    for (int fm = 0; fm < 4; fm++) {
        int r0 = m0 + wm + fm * 16 + (lane >> 2);
        #pragma unroll
        for (int fn = 0; fn < 4; fn++) {
            int c0 = n0 + wn + fn * 8 + (lane & 3) * 2;
            *reinterpret_cast<float2*>(&C[(size_t)r0 * LDC + c0]) =
                make_float2(acc[fm][fn][0], acc[fm][fn][1]);
            *reinterpret_cast<float2*>(&C[(size_t)(r0 + 8) * LDC + c0]) =
                make_float2(acc[fm][fn][2], acc[fm][fn][3]);
        }
    }

    // ---- fused BN stats: per-column partials from regs -> smem atomics -> global ----
    if (STATS) {
        #pragma unroll
        for (int fn = 0; fn < 4; fn++) {
            int cl = wn + fn * 8 + (lane & 3) * 2;   // local column (0..127)
            float s0 = 0.f, q0s = 0.f, s1 = 0.f, q1s = 0.f;
            #pragma unroll
            for (int fm = 0; fm < 4; fm++) {
                float* d = acc[fm][fn];
                s0 += d[0] + d[2];
                q0s = fmaf(d[0], d[0], fmaf(d[2], d[2], q0s));
                s1 += d[1] + d[3];
                q1s = fmaf(d[1], d[1], fmaf(d[3], d[3], q1s));
            }
            atomicAdd(&csum[cl], s0);
            atomicAdd(&csq[cl], q0s);
            atomicAdd(&csum[cl + 1], s1);
            atomicAdd(&csq[cl + 1], q1s);
        }
        __syncthreads();
        if (tid < 128) {
            atomicAdd(&g_sum[n0 + tid], csum[tid]);
            atomicAdd(&g_sumsq[n0 + tid], csq[tid]);
        }
    }
}

// ---------------- BN finalize ----------------
__global__ void bn_finalize_kernel(const float* __restrict__ bn_scale) {
    int f = blockIdx.x * blockDim.x + threadIdx.x;
    if (f < FF) {
        float mean = g_sum[f] * (1.f / MM);
        float var  = g_sumsq[f] * (1.f / MM) - mean * mean;
        float r = rsqrtf(var + 1e-5f);
        float a = r * bn_scale[f];
        g_affa[f] = a;
        g_affb[f] = -mean * a;
    }
}

// ---------------- normalize x in place ----------------
__global__ __launch_bounds__(256) void normalize_kernel() {
    size_t i = (size_t)blockIdx.x * 256 + threadIdx.x;
    int c4 = (int)(i & 255);
    float4 v = reinterpret_cast<float4*>(g_x)[i];
    float4 a = reinterpret_cast<float4*>(g_affa)[c4];
    float4 bb = reinterpret_cast<float4*>(g_affb)[c4];
    v.x = fmaf(v.x, a.x, bb.x);
    v.y = fmaf(v.y, a.y, bb.y);
    v.z = fmaf(v.z, a.z, bb.z);
    v.w = fmaf(v.w, a.w, bb.w);
    reinterpret_cast<float4*>(g_x)[i] = v;
}

// ---------------- fused flash attention (r14 verbatim): QT=56, KT=64, 224 thr, 4x4 ----------------
#define EXP_SHIFT 20.0f
__global__ __launch_bounds__(224, 4) void attention_kernel(
    const float* __restrict__ bias, float* __restrict__ out)
{
    __shared__ __align__(16) float Qs[56 * 32];
    __shared__ __align__(16) float Ks[64 * 32];
    __shared__ __align__(16) float Vs[64 * 64];
    __shared__ __align__(16) float Ss[56 * 68];

    const int tid = threadIdx.x;
    const int tx = tid & 15, ty = tid >> 4;
    const int tx4 = tx * 4, ty4 = ty * 4;
    const int q0 = blockIdx.x * 56;
    const int h  = blockIdx.y;
    const int b  = blockIdx.z;

    #pragma unroll
    for (int r = 0; r < 2; r++) {
        int f = tid + r * 224;
        int q = f >> 3, d4 = f & 7;
        float4 v = *reinterpret_cast<const float4*>(
            &g_x[(size_t)(b * NN + q0 + q) * FF + h * 32 + d4 * 4]);
        *reinterpret_cast<float4*>(&Qs[q * 32 + d4 * 4]) = v;
    }

    u64 acc2[4][2] = {};
    float lacc[4] = {0.f, 0.f, 0.f, 0.f};

    for (int kc = 0; kc < 13; kc++) {
        const int k0 = kc * 64;
        __syncthreads();

        for (int f = tid; f < 512; f += 224) {
            int k = f >> 3, d4 = f & 7;
            int row = k0 + k;
            float4 v = make_float4(0.f, 0.f, 0.f, 0.f);
            if (row < NN)
                v = *reinterpret_cast<const float4*>(
                    &g_x[(size_t)(b * NN + row) * FF + 256 + h * 32 + d4 * 4]);
            *reinterpret_cast<float4*>(&Ks[k * 32 + ((d4 ^ ((k >> 2) & 7)) << 2)]) = v;
        }
        for (int f = tid; f < 1024; f += 224) {
            int k = f >> 4, t = f & 15;
            int part = t >> 3, d4 = t & 7;
            int row = k0 + k;
            float4 v = make_float4(0.f, 0.f, 0.f, 0.f);
            if (row < NN)
                v = *reinterpret_cast<const float4*>(
                    &g_x[(size_t)(b * NN + row) * FF + 512 + part * 256 + h * 32 + d4 * 4]);
            *reinterpret_cast<float4*>(&Vs[k * 64 + part * 32 + d4 * 4]) = v;
        }
        __syncthreads();

        {
            u64 s2[4][4] = {};
            #pragma unroll
            for (int dq = 0; dq < 8; dq++) {
                ulonglong2 kb[4];
                #pragma unroll
                for (int j = 0; j < 4; j++)
                    kb[j] = *reinterpret_cast<const ulonglong2*>(
                        &Ks[(tx4 + j) * 32 + ((dq ^ (tx & 7)) << 2)]);
                #pragma unroll
                for (int i = 0; i < 4; i++) {
                    ulonglong2 qa = *reinterpret_cast<const ulonglong2*>(
                        &Qs[(ty4 + i) * 32 + dq * 4]);
                    #pragma unroll
                    for (int j = 0; j < 4; j++) {
                        fma2(s2[i][j], qa.x, kb[j].x);
                        fma2(s2[i][j], qa.y, kb[j].y);
                    }
                }
            }
            if (k0 + tx4 + 3 < NN) {
                #pragma unroll
                for (int i = 0; i < 4; i++) {
                    float4 bi = *reinterpret_cast<const float4*>(
                        &bias[(size_t)(q0 + ty4 + i) * NN + k0 + tx4]);
                    float lo, hi, p0, p1, p2, p3;
                    upk2(s2[i][0], lo, hi); p0 = __expf(lo + hi + bi.x - EXP_SHIFT);
                    upk2(s2[i][1], lo, hi); p1 = __expf(lo + hi + bi.y - EXP_SHIFT);
                    upk2(s2[i][2], lo, hi); p2 = __expf(lo + hi + bi.z - EXP_SHIFT);
                    upk2(s2[i][3], lo, hi); p3 = __expf(lo + hi + bi.w - EXP_SHIFT);
                    *reinterpret_cast<float4*>(&Ss[(ty4 + i) * 68 + tx4]) =
                        make_float4(p0, p1, p2, p3);
                }
            } else {
                #pragma unroll
                for (int i = 0; i < 4; i++)
                    *reinterpret_cast<float4*>(&Ss[(ty4 + i) * 68 + tx4]) =
                        make_float4(0.f, 0.f, 0.f, 0.f);
            }
        }
        __syncthreads();

        #pragma unroll
        for (int kk = 0; kk < 16; kk++) {
            float4 P[4];
            #pragma unroll
            for (int i = 0; i < 4; i++)
                P[i] = *reinterpret_cast<const float4*>(&Ss[(ty4 + i) * 68 + kk * 4]);
            if (tx == kk) {
                #pragma unroll
                for (int i = 0; i < 4; i++)
                    lacc[i] += (P[i].x + P[i].y) + (P[i].z + P[i].w);
            }
            #pragma unroll
            for (int c = 0; c < 4; c++) {
                ulonglong2 vv = *reinterpret_cast<const ulonglong2*>(
                    &Vs[(kk * 4 + c) * 64 + tx4]);
                #pragma unroll
                for (int i = 0; i < 4; i++) {
                    float p = (c == 0) ? P[i].x : (c == 1) ? P[i].y : (c == 2) ? P[i].z : P[i].w;
                    u64 pp = pk2(p, p);
                    fma2(acc2[i][0], pp, vv.x);
                    fma2(acc2[i][1], pp, vv.y);
                }
            }
        }
    }

    #pragma unroll
    for (int i = 0; i < 4; i++) {
        #pragma unroll
        for (int d = 1; d < 16; d <<= 1)
            lacc[i] += __shfl_xor_sync(0xffffffffu, lacc[i], d);
    }

    #pragma unroll
    for (int i = 0; i < 4; i++) {
        int q = ty4 + i;
        float inv = 1.0f / lacc[i];
        float v0, v1, v2, v3;
        upk2(acc2[i][0], v0, v1);
        upk2(acc2[i][1], v2, v3);
        v0 *= inv; v1 *= inv; v2 *= inv; v3 *= inv;
        float o[4];
        o[0] = v0 * __saturatef((v0 + 3.0f) * (1.0f / 6.0f));
        o[1] = v1 * __saturatef((v1 + 3.0f) * (1.0f / 6.0f));
        o[2] = v2 * __saturatef((v2 + 3.0f) * (1.0f / 6.0f));
        o[3] = v3 * __saturatef((v3 + 3.0f) * (1.0f / 6.0f));
        *reinterpret_cast<float4*>(&out[((size_t)(b * NN + q0 + q)) * 512 + h * 64 + tx4]) =
            make_float4(o[0], o[1], o[2], o[3]);
    }
}

// ---------------- launch ----------------
extern "C" void kernel_launch(void* const* d_in, const int* in_sizes, int n_in,
                              void* d_out, int out_size) {
    const float* inputs    = (const float*)d_in[0];
    const float* w_qkv     = (const float*)d_in[1];
    const float* bn_scale  = (const float*)d_in[2];
    const float* attn_bias = (const float*)d_in[3];
    const float* w_out     = (const float*)d_in[4];
    float* out = (float*)d_out;

    float *px, *pattn;
    cudaGetSymbolAddress((void**)&px, g_x);
    cudaGetSymbolAddress((void**)&pattn, g_attn);
    __nv_bfloat16 *pwqh, *pwql, *pwoh, *pwol;
    cudaGetSymbolAddress((void**)&pwqh, g_wq_h);
    cudaGetSymbolAddress((void**)&pwql, g_wq_l);
    cudaGetSymbolAddress((void**)&pwoh, g_wo_h);
    cudaGetSymbolAddress((void**)&pwol, g_wo_l);

    zero_stats_kernel<<<4, 256>>>();
    conv_w_kernel<<<1024, 256>>>(w_qkv, w_out);
    // x = inputs @ w_qkv  (tensor-core bf16 split, fused BN stats)
    mma_gemm_kernel<256, 1024, 1024, true><<<dim3(196, 8), 256>>>(inputs, pwqh, pwql, px);
    bn_finalize_kernel<<<4, 256>>>(bn_scale);
    normalize_kernel<<<MM, 256>>>();
    attention_kernel<<<dim3(14, HEADS, BB), 224>>>(attn_bias, pattn);
    // out = attn @ w_out  (tensor-core bf16 split)
    mma_gemm_kernel<512, 256, 256, false><<<dim3(196, 2), 256>>>(pattn, pwoh, pwol, out);
}